// round 3
// baseline (speedup 1.0000x reference)
#include <cuda_runtime.h>
#include <cstdint>
#include <cstddef>

#define Bn 128
#define Tn 1024
#define Dn 48
#define Hn 256
#define NBLK 128
#define NTHR 256

// ---------------- device scratch (no allocations allowed) ----------------
__device__ float g_xT[Tn * Dn * Bn];                  // [t][d][b]
__device__ float g_o0[(size_t)Tn * 2 * Hn * Bn];      // [t][512][b]  layer0 outputs
__device__ float g_h[2][2][Hn * Bn];                  // [parity][dir][j][b]
__device__ unsigned g_cnt = 0;
__device__ unsigned g_rel = 0;

// ---------------- cp.async helpers ----------------
__device__ __forceinline__ void cp_async16(void* smem_dst, const void* gsrc) {
    unsigned dst = (unsigned)__cvta_generic_to_shared(smem_dst);
    asm volatile("cp.async.cg.shared.global [%0], [%1], 16;" :: "r"(dst), "l"(gsrc) : "memory");
}
__device__ __forceinline__ void cp_commit() { asm volatile("cp.async.commit_group;" ::: "memory"); }
__device__ __forceinline__ void cp_wait0()  { asm volatile("cp.async.wait_group 0;"  ::: "memory"); }

// ---------------- grid barrier (replay-safe: monotonic release counter) ----------------
__device__ __forceinline__ void gbar(unsigned& r_last) {
    __threadfence();
    __syncthreads();
    if (threadIdx.x == 0) {
        unsigned arrived = atomicAdd(&g_cnt, 1);
        if (arrived == NBLK - 1) {
            atomicExch(&g_cnt, 0);
            __threadfence();
            unsigned old = atomicAdd(&g_rel, 1);
            r_last = old + 1;
        } else {
            unsigned cur;
            do { cur = *((volatile unsigned*)&g_rel); } while (cur == r_last);
            r_last = cur;
        }
    }
    __syncthreads();
}

// ---------------- helpers ----------------
__global__ void transpose_x_kernel(const float* __restrict__ x) {
    int idx = blockIdx.x * blockDim.x + threadIdx.x;
    if (idx >= Tn * Dn * Bn) return;
    int b = idx & (Bn - 1);
    int rem = idx >> 7;
    int d = rem % Dn;
    int t = rem / Dn;
    g_xT[idx] = x[((size_t)b * Tn + t) * Dn + d];
}

__device__ __forceinline__ float sigmoidf_(float v) { return 1.0f / (1.0f + __expf(-v)); }

// ================= persistent LSTM =================
// smem layout (floats):
//   s_w    [16][K]         (K = 768 max -> 12288)
//   s_in   [2][128][128]   (32768)
//   s_part [4][16][128]    (8192)
//   s_g    [16][128]       (2048)
//   s_bias [16]
#define SW_OFF    0
#define SIN_OFF   (16 * 768)
#define SPART_OFF (SIN_OFF + 2 * 128 * 128)
#define SG_OFF    (SPART_OFF + 4 * 16 * 128)
#define SBIAS_OFF (SG_OFF + 16 * 128)
#define SMEM_FLOATS (SBIAS_OFF + 32)

template<int IN>
__device__ __forceinline__ void load_weights(float* s_w, const float* Wih, const float* Whh, int j0, int tid) {
    constexpr int K = IN + Hn;
    constexpr int K4 = K / 4;
    for (int i = tid; i < 16 * K4; i += NTHR) {
        int r  = i / K4;
        int gk = (i - r * K4) * 4;
        int grow = (r >> 2) * Hn + j0 + (r & 3);
        float4 v = (gk < IN)
            ? *(const float4*)(Wih + (size_t)grow * IN + gk)
            : *(const float4*)(Whh + (size_t)grow * Hn + (gk - IN));
        *(float4*)(s_w + r * K + gk) = v;
    }
}

template<int IN>
__device__ __forceinline__ void stage_chunk(float* sbuf, const float* xrow, const float* hread,
                                            int kc, int klen, int tid) {
    int n4 = klen * 32;                           // float4 slots (128 batch = 32 float4)
    for (int i = tid; i < n4; i += NTHR) {
        int kk = i >> 5;
        int b4 = (i & 31) * 4;
        int gk = kc + kk;
        const float* src = (gk < IN) ? (xrow + (size_t)gk * Bn + b4)
                                     : (hread + (size_t)(gk - IN) * Bn + b4);
        cp_async16(sbuf + kk * Bn + b4, src);
    }
}

template<int IN, bool L0P>
__device__ __forceinline__ void do_step(float* smem, const float* xin, int t, int dir, int j0,
                                        int tid, int len, float c_reg[2], float h_reg[2],
                                        const float* hread, float* hwrite)
{
    constexpr int K  = IN + Hn;
    constexpr int NC = (K + 127) / 128;
    float* s_w    = smem + SW_OFF;
    float* s_in   = smem + SIN_OFF;
    float* s_part = smem + SPART_OFF;
    float* s_g    = smem + SG_OFF;
    float* s_bias = smem + SBIAS_OFF;

    const int kg  = tid >> 6;            // k-group 0..3
    const int lid = tid & 63;
    const int rg  = lid >> 4;            // row group 0..3 (4 rows each)
    const int b0  = (lid & 15) * 8;      // batch base
    const float* xrow = xin + (size_t)t * IN * Bn;

    float acc[4][8];
#pragma unroll
    for (int u = 0; u < 4; ++u)
#pragma unroll
        for (int j = 0; j < 8; ++j) acc[u][j] = 0.0f;

    const float* w0r = s_w + (rg * 4 + 0) * K;
    const float* w1r = s_w + (rg * 4 + 1) * K;
    const float* w2r = s_w + (rg * 4 + 2) * K;
    const float* w3r = s_w + (rg * 4 + 3) * K;

    // pipeline: stage chunk 0, then wait/issue-next/consume
    stage_chunk<IN>(s_in, xrow, hread, 0, (K < 128 ? K : 128), tid);
    cp_commit();
#pragma unroll
    for (int c = 0; c < NC; ++c) {
        cp_wait0();
        __syncthreads();
        if (c + 1 < NC) {
            int kc = (c + 1) * 128;
            int kl = (K - kc < 128) ? (K - kc) : 128;
            stage_chunk<IN>(s_in + ((c + 1) & 1) * (128 * Bn), xrow, hread, kc, kl, tid);
            cp_commit();
        }
        const int klen = (K - c * 128 < 128) ? (K - c * 128) : 128;
        const int span = klen >> 2;
        const float* inb = s_in + (c & 1) * (128 * Bn);
        const int kst  = kg * span;
        const int kgl0 = c * 128 + kst;
#pragma unroll 4
        for (int kk = 0; kk < span; ++kk) {
            float a0 = w0r[kgl0 + kk];
            float a1 = w1r[kgl0 + kk];
            float a2 = w2r[kgl0 + kk];
            float a3 = w3r[kgl0 + kk];
            const float* ip = inb + (kst + kk) * Bn + b0;
            float4 v0 = *(const float4*)ip;
            float4 v1 = *(const float4*)(ip + 4);
#define FMA8(U, A)                                                       \
            acc[U][0] += A * v0.x; acc[U][1] += A * v0.y;                \
            acc[U][2] += A * v0.z; acc[U][3] += A * v0.w;                \
            acc[U][4] += A * v1.x; acc[U][5] += A * v1.y;                \
            acc[U][6] += A * v1.z; acc[U][7] += A * v1.w;
            FMA8(0, a0) FMA8(1, a1) FMA8(2, a2) FMA8(3, a3)
#undef FMA8
        }
    }

    // write partials: s_part[kg][r][b]
#pragma unroll
    for (int u = 0; u < 4; ++u) {
        float* p = s_part + (kg * 16 + rg * 4 + u) * Bn + b0;
        *(float4*)p       = make_float4(acc[u][0], acc[u][1], acc[u][2], acc[u][3]);
        *(float4*)(p + 4) = make_float4(acc[u][4], acc[u][5], acc[u][6], acc[u][7]);
    }
    __syncthreads();

    // reduce k-groups + bias -> s_g[r][b]
#pragma unroll
    for (int i = 0; i < 8; ++i) {
        int idx = tid + i * NTHR;
        s_g[idx] = s_bias[idx >> 7] + s_part[idx] + s_part[2048 + idx]
                 + s_part[4096 + idx] + s_part[6144 + idx];
    }
    __syncthreads();

    // pointwise LSTM update, state in registers
#pragma unroll
    for (int i = 0; i < 2; ++i) {
        int idx = tid + i * NTHR;
        int u = idx >> 7;
        int b = idx & (Bn - 1);
        float ig = sigmoidf_(s_g[(0 * 4 + u) * Bn + b]);
        float fg = sigmoidf_(s_g[(1 * 4 + u) * Bn + b]);
        float gg = tanhf    (s_g[(2 * 4 + u) * Bn + b]);
        float og = sigmoidf_(s_g[(3 * 4 + u) * Bn + b]);
        float cnew = fg * c_reg[i] + ig * gg;
        float hnew = og * tanhf(cnew);
        bool m = (t < len);
        c_reg[i] = m ? cnew : c_reg[i];
        float hw = m ? hnew : h_reg[i];
        h_reg[i] = hw;
        __stcg(&hwrite[(j0 + u) * Bn + b], hw);
        if (L0P)
            __stcg(&g_o0[((size_t)t * 2 * Hn + dir * Hn + j0 + u) * Bn + b], m ? hnew : 0.0f);
    }
}

template<int IN, bool L0P>
__device__ __forceinline__ void run_phase(float* smem,
    const float* Wih_f, const float* Whh_f, const float* bih_f, const float* bhh_f,
    const float* Wih_b, const float* Whh_b, const float* bih_b, const float* bhh_b,
    const float* xin, int dir, int j0, int tid, int len, unsigned& r_last)
{
    const float* Wih = dir ? Wih_b : Wih_f;
    const float* Whh = dir ? Whh_b : Whh_f;
    const float* bih = dir ? bih_b : bih_f;
    const float* bhh = dir ? bhh_b : bhh_f;

    load_weights<IN>(smem + SW_OFF, Wih, Whh, j0, tid);
    if (tid < 16) {
        int grow = (tid >> 2) * Hn + j0 + (tid & 3);
        (smem + SBIAS_OFF)[tid] = bih[grow] + bhh[grow];
    }

    float c_reg[2] = {0.0f, 0.0f};
    float h_reg[2] = {0.0f, 0.0f};
#pragma unroll
    for (int i = 0; i < 2; ++i) {
        int idx = tid + i * NTHR;
        int u = idx >> 7;
        int b = idx & (Bn - 1);
        __stcg(&g_h[0][dir][(j0 + u) * Bn + b], 0.0f);
        __stcg(&g_h[1][dir][(j0 + u) * Bn + b], 0.0f);
    }
    gbar(r_last);

    for (int s = 0; s < Tn; ++s) {
        int t = dir ? (Tn - 1 - s) : s;
        const float* hread  = g_h[s & 1][dir];
        float*       hwrite = g_h[(s + 1) & 1][dir];
        do_step<IN, L0P>(smem, xin, t, dir, j0, tid, len, c_reg, h_reg, hread, hwrite);
        gbar(r_last);
    }
}

__global__ void __launch_bounds__(NTHR, 1) lstm_persistent_kernel(
    const float* __restrict__ w_ih_l0f, const float* __restrict__ w_hh_l0f,
    const float* __restrict__ b_ih_l0f, const float* __restrict__ b_hh_l0f,
    const float* __restrict__ w_ih_l0b, const float* __restrict__ w_hh_l0b,
    const float* __restrict__ b_ih_l0b, const float* __restrict__ b_hh_l0b,
    const float* __restrict__ w_ih_l1f, const float* __restrict__ w_hh_l1f,
    const float* __restrict__ b_ih_l1f, const float* __restrict__ b_hh_l1f,
    const float* __restrict__ w_ih_l1b, const float* __restrict__ w_hh_l1b,
    const float* __restrict__ b_ih_l1b, const float* __restrict__ b_hh_l1b,
    const int* __restrict__ lengths)
{
    extern __shared__ float smem[];
    const int tid = threadIdx.x;
    const int dir = blockIdx.x >> 6;           // 0..1
    const int j0  = (blockIdx.x & 63) * 4;     // 4 hidden units per block
    const int len = lengths[tid & (Bn - 1)];

    unsigned r_last = *((volatile unsigned*)&g_rel);   // safe: first release needs all blocks

    run_phase<Dn, true>(smem,
        w_ih_l0f, w_hh_l0f, b_ih_l0f, b_hh_l0f,
        w_ih_l0b, w_hh_l0b, b_ih_l0b, b_hh_l0b,
        g_xT, dir, j0, tid, len, r_last);

    run_phase<2 * Hn, false>(smem,
        w_ih_l1f, w_hh_l1f, b_ih_l1f, b_hh_l1f,
        w_ih_l1b, w_hh_l1b, b_ih_l1b, b_hh_l1b,
        g_o0, dir, j0, tid, len, r_last);
}

// ---------------- FC head ----------------
__global__ void head_kernel(const float* __restrict__ fc1_w, const float* __restrict__ fc1_b,
                            const float* __restrict__ fc2_w, const float* __restrict__ fc2_b,
                            float* __restrict__ out)
{
    __shared__ float s_h[2 * Hn];
    __shared__ float s_r[256];
    int b = blockIdx.x;
    int tid = threadIdx.x;
    // final L1 states: 1024 steps -> parity 0
    for (int k = tid; k < 2 * Hn; k += 256)
        s_h[k] = (k < Hn) ? g_h[0][0][k * Bn + b] : g_h[0][1][(k - Hn) * Bn + b];
    __syncthreads();

    const float* wr = fc1_w + (size_t)tid * 2 * Hn;
    float sum = fc1_b[tid];
#pragma unroll 8
    for (int k = 0; k < 2 * Hn; ++k) sum += wr[k] * s_h[k];
    s_r[tid] = fmaxf(sum, 0.0f) * fc2_w[tid];
    __syncthreads();
    for (int st = 128; st > 0; st >>= 1) {
        if (tid < st) s_r[tid] += s_r[tid + st];
        __syncthreads();
    }
    if (tid == 0) out[b] = s_r[0] + fc2_b[0];
}

// ---------------- launch ----------------
extern "C" void kernel_launch(void* const* d_in, const int* in_sizes, int n_in,
                              void* d_out, int out_size)
{
    const float* x        = (const float*)d_in[0];
    const int*   lengths  = (const int*)  d_in[1];
    const float* w_ih_l0f = (const float*)d_in[2];
    const float* w_hh_l0f = (const float*)d_in[3];
    const float* b_ih_l0f = (const float*)d_in[4];
    const float* b_hh_l0f = (const float*)d_in[5];
    const float* w_ih_l0b = (const float*)d_in[6];
    const float* w_hh_l0b = (const float*)d_in[7];
    const float* b_ih_l0b = (const float*)d_in[8];
    const float* b_hh_l0b = (const float*)d_in[9];
    const float* w_ih_l1f = (const float*)d_in[10];
    const float* w_hh_l1f = (const float*)d_in[11];
    const float* b_ih_l1f = (const float*)d_in[12];
    const float* b_hh_l1f = (const float*)d_in[13];
    const float* w_ih_l1b = (const float*)d_in[14];
    const float* w_hh_l1b = (const float*)d_in[15];
    const float* b_ih_l1b = (const float*)d_in[16];
    const float* b_hh_l1b = (const float*)d_in[17];
    const float* fc1_w    = (const float*)d_in[18];
    const float* fc1_b    = (const float*)d_in[19];
    const float* fc2_w    = (const float*)d_in[20];
    const float* fc2_b    = (const float*)d_in[21];

    const size_t smem_bytes = (size_t)SMEM_FLOATS * sizeof(float);   // ~216 KB
    static bool attr_done = false;
    if (!attr_done) {
        cudaFuncSetAttribute((const void*)lstm_persistent_kernel,
                             cudaFuncAttributeMaxDynamicSharedMemorySize, (int)smem_bytes);
        attr_done = true;
    }

    transpose_x_kernel<<<(Tn * Dn * Bn + 255) / 256, 256>>>(x);

    lstm_persistent_kernel<<<NBLK, NTHR, smem_bytes>>>(
        w_ih_l0f, w_hh_l0f, b_ih_l0f, b_hh_l0f,
        w_ih_l0b, w_hh_l0b, b_ih_l0b, b_hh_l0b,
        w_ih_l1f, w_hh_l1f, b_ih_l1f, b_hh_l1f,
        w_ih_l1b, w_hh_l1b, b_ih_l1b, b_hh_l1b,
        lengths);

    head_kernel<<<Bn, 256>>>(fc1_w, fc1_b, fc2_w, fc2_b, (float*)d_out);
}

// round 4
// speedup vs baseline: 1.0117x; 1.0117x over previous
#include <cuda_runtime.h>
#include <cstdint>
#include <cstddef>

#define Bn 128
#define Tn 1024
#define Dn 48
#define Hn 256
#define NBLK 128
#define NTHR 256

typedef unsigned long long ull;

// ---------------- device scratch (no allocations allowed) ----------------
__device__ float g_xT[Tn * Dn * Bn];                  // [t][d][b]
__device__ float g_o0[(size_t)Tn * 2 * Hn * Bn];      // [t][512][b]  layer0 outputs
__device__ float g_h[2][2][Hn * Bn];                  // [parity][dir][j][b]
__device__ unsigned g_cnt_dir[2] = {0, 0};
__device__ unsigned g_rel_dir[2] = {0, 0};
__device__ unsigned g_cnt_all = 0;
__device__ unsigned g_rel_all = 0;

// ---------------- packed f32x2 helpers ----------------
__device__ __forceinline__ void ffma2(ull& d, ull a, ull b) {
    asm("fma.rn.f32x2 %0, %1, %2, %0;" : "+l"(d) : "l"(a), "l"(b));
}
__device__ __forceinline__ ull pack2(float a) {
    ull r;
    asm("mov.b64 %0, {%1, %1};" : "=l"(r) : "f"(a));
    return r;
}

// ---------------- cp.async helpers ----------------
__device__ __forceinline__ void cp_async16(void* smem_dst, const void* gsrc) {
    unsigned dst = (unsigned)__cvta_generic_to_shared(smem_dst);
    asm volatile("cp.async.cg.shared.global [%0], [%1], 16;" :: "r"(dst), "l"(gsrc) : "memory");
}
__device__ __forceinline__ void cp_commit() { asm volatile("cp.async.commit_group;" ::: "memory"); }
__device__ __forceinline__ void cp_wait0()  { asm volatile("cp.async.wait_group 0;"  ::: "memory"); }

// ---------------- grid barrier (replay-safe monotonic release counter) ----------------
__device__ __forceinline__ void gbar_n(unsigned* cnt, unsigned* rel, unsigned n, unsigned& r_last) {
    __threadfence();
    __syncthreads();
    if (threadIdx.x == 0) {
        unsigned arrived = atomicAdd(cnt, 1);
        if (arrived == n - 1) {
            atomicExch(cnt, 0);
            __threadfence();
            r_last = atomicAdd(rel, 1) + 1;
        } else {
            unsigned cur;
            do { cur = *((volatile unsigned*)rel); } while (cur == r_last);
            r_last = cur;
        }
    }
    __syncthreads();
}

// ---------------- helpers ----------------
__global__ void transpose_x_kernel(const float* __restrict__ x) {
    int idx = blockIdx.x * blockDim.x + threadIdx.x;
    if (idx >= Tn * Dn * Bn) return;
    int b = idx & (Bn - 1);
    int rem = idx >> 7;
    int d = rem % Dn;
    int t = rem / Dn;
    g_xT[idx] = x[((size_t)b * Tn + t) * Dn + d];
}

__device__ __forceinline__ float sigmoidf_(float v) { return 1.0f / (1.0f + __expf(-v)); }

// ================= persistent LSTM =================
// smem layout (floats):
//   s_w    [K][16]         (K = 768 max -> 12288)   weights interleaved by row
//   s_in   [2][128][128]   (32768)
//   s_part [4][16][128]    (8192)
//   s_g    [16][128]       (2048)
//   s_bias [16] (+pad)
#define SW_OFF    0
#define SIN_OFF   (768 * 16)
#define SPART_OFF (SIN_OFF + 2 * 128 * 128)
#define SG_OFF    (SPART_OFF + 4 * 16 * 128)
#define SBIAS_OFF (SG_OFF + 16 * 128)
#define SMEM_FLOATS (SBIAS_OFF + 32)

template<int IN>
__device__ __forceinline__ void load_weights(float* s_w, const float* Wih, const float* Whh, int j0, int tid) {
    constexpr int K = IN + Hn;
    constexpr int K4 = K / 4;
    for (int i = tid; i < 16 * K4; i += NTHR) {
        int r  = i / K4;
        int gk = (i - r * K4) * 4;
        int grow = (r >> 2) * Hn + j0 + (r & 3);       // gate*H + unit
        float4 v = (gk < IN)
            ? *(const float4*)(Wih + (size_t)grow * IN + gk)
            : *(const float4*)(Whh + (size_t)grow * Hn + (gk - IN));
        s_w[(gk + 0) * 16 + r] = v.x;
        s_w[(gk + 1) * 16 + r] = v.y;
        s_w[(gk + 2) * 16 + r] = v.z;
        s_w[(gk + 3) * 16 + r] = v.w;
    }
}

template<int IN>
__device__ __forceinline__ void stage_chunk(float* sbuf, const float* xrow, const float* hread,
                                            int kc, int klen, int tid) {
    int n4 = klen * 32;                           // float4 slots (128 batch = 32 float4)
    for (int i = tid; i < n4; i += NTHR) {
        int kk = i >> 5;
        int b4 = (i & 31) * 4;
        int gk = kc + kk;
        const float* src = (gk < IN) ? (xrow + (size_t)gk * Bn + b4)
                                     : (hread + (size_t)(gk - IN) * Bn + b4);
        cp_async16(sbuf + kk * Bn + b4, src);
    }
}

template<int IN, bool L0P>
__device__ __forceinline__ void do_step(float* smem, const float* xin, int t, int dir, int j0,
                                        int tid, int len, float c_reg[2], float h_reg[2],
                                        const float* hread, float* hwrite)
{
    constexpr int K  = IN + Hn;
    constexpr int NC = (K + 127) / 128;
    float* s_w    = smem + SW_OFF;
    float* s_in   = smem + SIN_OFF;
    float* s_part = smem + SPART_OFF;
    float* s_g    = smem + SG_OFF;
    float* s_bias = smem + SBIAS_OFF;

    const int kg  = tid >> 6;            // k-group 0..3
    const int lid = tid & 63;
    const int rg  = lid >> 4;            // row group 0..3 (4 rows each)
    const int b0  = (lid & 15) * 8;      // batch base (8 batch = 4 f32x2 pairs)
    const float* xrow = xin + (size_t)t * IN * Bn;

    ull acc[4][4];
#pragma unroll
    for (int u = 0; u < 4; ++u)
#pragma unroll
        for (int p = 0; p < 4; ++p) acc[u][p] = 0ull;

    // pipeline: stage chunk 0, then wait/issue-next/consume
    stage_chunk<IN>(s_in, xrow, hread, 0, (K < 128 ? K : 128), tid);
    cp_commit();
#pragma unroll
    for (int c = 0; c < NC; ++c) {
        cp_wait0();
        __syncthreads();
        if (c + 1 < NC) {
            int kc = (c + 1) * 128;
            int kl = (K - kc < 128) ? (K - kc) : 128;
            stage_chunk<IN>(s_in + ((c + 1) & 1) * (128 * Bn), xrow, hread, kc, kl, tid);
            cp_commit();
        }
        const int klen = (K - c * 128 < 128) ? (K - c * 128) : 128;
        const int span = klen >> 2;          // k per k-group in this chunk
        const float* inb = s_in + (c & 1) * (128 * Bn);
        const int kst  = kg * span;          // within-chunk k start
        const int kbase = c * 128 + kst;     // global k start (s_w index)

#pragma unroll 4
        for (int kk = 0; kk < span; ++kk) {
            float4 wv = *(const float4*)(s_w + (size_t)(kbase + kk) * 16 + rg * 4);
            ull wa0 = pack2(wv.x);
            ull wa1 = pack2(wv.y);
            ull wa2 = pack2(wv.z);
            ull wa3 = pack2(wv.w);
            const float* ip = inb + (kst + kk) * Bn + b0;
            ulonglong2 p0 = *(const ulonglong2*)(ip);
            ulonglong2 p1 = *(const ulonglong2*)(ip + 4);
            ffma2(acc[0][0], wa0, p0.x); ffma2(acc[0][1], wa0, p0.y);
            ffma2(acc[0][2], wa0, p1.x); ffma2(acc[0][3], wa0, p1.y);
            ffma2(acc[1][0], wa1, p0.x); ffma2(acc[1][1], wa1, p0.y);
            ffma2(acc[1][2], wa1, p1.x); ffma2(acc[1][3], wa1, p1.y);
            ffma2(acc[2][0], wa2, p0.x); ffma2(acc[2][1], wa2, p0.y);
            ffma2(acc[2][2], wa2, p1.x); ffma2(acc[2][3], wa2, p1.y);
            ffma2(acc[3][0], wa3, p0.x); ffma2(acc[3][1], wa3, p0.y);
            ffma2(acc[3][2], wa3, p1.x); ffma2(acc[3][3], wa3, p1.y);
        }
    }

    // write partials: s_part[kg][r][b]  (pairs are batch-adjacent, layout matches)
#pragma unroll
    for (int u = 0; u < 4; ++u) {
        float* p = s_part + (size_t)(kg * 16 + rg * 4 + u) * Bn + b0;
        *(ulonglong2*)p       = make_ulonglong2(acc[u][0], acc[u][1]);
        *(ulonglong2*)(p + 4) = make_ulonglong2(acc[u][2], acc[u][3]);
    }
    __syncthreads();

    // reduce k-groups + bias -> s_g[r][b]
#pragma unroll
    for (int i = 0; i < 8; ++i) {
        int idx = tid + i * NTHR;
        s_g[idx] = s_bias[idx >> 7] + s_part[idx] + s_part[2048 + idx]
                 + s_part[4096 + idx] + s_part[6144 + idx];
    }
    __syncthreads();

    // pointwise LSTM update, state in registers
#pragma unroll
    for (int i = 0; i < 2; ++i) {
        int idx = tid + i * NTHR;
        int u = idx >> 7;
        int b = idx & (Bn - 1);
        float ig = sigmoidf_(s_g[(0 * 4 + u) * Bn + b]);
        float fg = sigmoidf_(s_g[(1 * 4 + u) * Bn + b]);
        float gg = tanhf    (s_g[(2 * 4 + u) * Bn + b]);
        float og = sigmoidf_(s_g[(3 * 4 + u) * Bn + b]);
        float cnew = fg * c_reg[i] + ig * gg;
        float hnew = og * tanhf(cnew);
        bool m = (t < len);
        c_reg[i] = m ? cnew : c_reg[i];
        float hw = m ? hnew : h_reg[i];
        h_reg[i] = hw;
        __stcg(&hwrite[(j0 + u) * Bn + b], hw);
        if (L0P)
            __stcg(&g_o0[((size_t)t * 2 * Hn + dir * Hn + j0 + u) * Bn + b], m ? hnew : 0.0f);
    }
}

template<int IN, bool L0P>
__device__ __forceinline__ void run_phase(float* smem,
    const float* Wih_f, const float* Whh_f, const float* bih_f, const float* bhh_f,
    const float* Wih_b, const float* Whh_b, const float* bih_b, const float* bhh_b,
    const float* xin, int dir, int j0, int tid, int len, unsigned& r_dir)
{
    const float* Wih = dir ? Wih_b : Wih_f;
    const float* Whh = dir ? Whh_b : Whh_f;
    const float* bih = dir ? bih_b : bih_f;
    const float* bhh = dir ? bhh_b : bhh_f;

    load_weights<IN>(smem + SW_OFF, Wih, Whh, j0, tid);
    if (tid < 16) {
        int grow = (tid >> 2) * Hn + j0 + (tid & 3);
        (smem + SBIAS_OFF)[tid] = bih[grow] + bhh[grow];
    }

    float c_reg[2] = {0.0f, 0.0f};
    float h_reg[2] = {0.0f, 0.0f};
#pragma unroll
    for (int i = 0; i < 2; ++i) {
        int idx = tid + i * NTHR;
        int u = idx >> 7;
        int b = idx & (Bn - 1);
        __stcg(&g_h[0][dir][(j0 + u) * Bn + b], 0.0f);
        __stcg(&g_h[1][dir][(j0 + u) * Bn + b], 0.0f);
    }
    gbar_n(&g_cnt_dir[dir], &g_rel_dir[dir], NBLK / 2, r_dir);

    for (int s = 0; s < Tn; ++s) {
        int t = dir ? (Tn - 1 - s) : s;
        const float* hread  = g_h[s & 1][dir];
        float*       hwrite = g_h[(s + 1) & 1][dir];
        do_step<IN, L0P>(smem, xin, t, dir, j0, tid, len, c_reg, h_reg, hread, hwrite);
        gbar_n(&g_cnt_dir[dir], &g_rel_dir[dir], NBLK / 2, r_dir);
    }
}

__global__ void __launch_bounds__(NTHR, 1) lstm_persistent_kernel(
    const float* __restrict__ w_ih_l0f, const float* __restrict__ w_hh_l0f,
    const float* __restrict__ b_ih_l0f, const float* __restrict__ b_hh_l0f,
    const float* __restrict__ w_ih_l0b, const float* __restrict__ w_hh_l0b,
    const float* __restrict__ b_ih_l0b, const float* __restrict__ b_hh_l0b,
    const float* __restrict__ w_ih_l1f, const float* __restrict__ w_hh_l1f,
    const float* __restrict__ b_ih_l1f, const float* __restrict__ b_hh_l1f,
    const float* __restrict__ w_ih_l1b, const float* __restrict__ w_hh_l1b,
    const float* __restrict__ b_ih_l1b, const float* __restrict__ b_hh_l1b,
    const int* __restrict__ lengths)
{
    extern __shared__ float smem[];
    const int tid = threadIdx.x;
    const int dir = blockIdx.x >> 6;           // 0..1
    const int j0  = (blockIdx.x & 63) * 4;     // 4 hidden units per block
    const int len = lengths[tid & (Bn - 1)];

    unsigned r_dir = *((volatile unsigned*)&g_rel_dir[dir]);
    unsigned r_all = *((volatile unsigned*)&g_rel_all);

    run_phase<Dn, true>(smem,
        w_ih_l0f, w_hh_l0f, b_ih_l0f, b_hh_l0f,
        w_ih_l0b, w_hh_l0b, b_ih_l0b, b_hh_l0b,
        g_xT, dir, j0, tid, len, r_dir);

    // phase boundary: L1 consumes g_o0 from BOTH directions
    gbar_n(&g_cnt_all, &g_rel_all, NBLK, r_all);

    run_phase<2 * Hn, false>(smem,
        w_ih_l1f, w_hh_l1f, b_ih_l1f, b_hh_l1f,
        w_ih_l1b, w_hh_l1b, b_ih_l1b, b_hh_l1b,
        g_o0, dir, j0, tid, len, r_dir);
}

// ---------------- FC head ----------------
__global__ void head_kernel(const float* __restrict__ fc1_w, const float* __restrict__ fc1_b,
                            const float* __restrict__ fc2_w, const float* __restrict__ fc2_b,
                            float* __restrict__ out)
{
    __shared__ float s_h[2 * Hn];
    __shared__ float s_r[256];
    int b = blockIdx.x;
    int tid = threadIdx.x;
    // final L1 states: 1024 steps -> parity 0
    for (int k = tid; k < 2 * Hn; k += 256)
        s_h[k] = (k < Hn) ? g_h[0][0][k * Bn + b] : g_h[0][1][(k - Hn) * Bn + b];
    __syncthreads();

    const float* wr = fc1_w + (size_t)tid * 2 * Hn;
    float sum = fc1_b[tid];
#pragma unroll 8
    for (int k = 0; k < 2 * Hn; ++k) sum += wr[k] * s_h[k];
    s_r[tid] = fmaxf(sum, 0.0f) * fc2_w[tid];
    __syncthreads();
    for (int st = 128; st > 0; st >>= 1) {
        if (tid < st) s_r[tid] += s_r[tid + st];
        __syncthreads();
    }
    if (tid == 0) out[b] = s_r[0] + fc2_b[0];
}

// ---------------- launch ----------------
extern "C" void kernel_launch(void* const* d_in, const int* in_sizes, int n_in,
                              void* d_out, int out_size)
{
    const float* x        = (const float*)d_in[0];
    const int*   lengths  = (const int*)  d_in[1];
    const float* w_ih_l0f = (const float*)d_in[2];
    const float* w_hh_l0f = (const float*)d_in[3];
    const float* b_ih_l0f = (const float*)d_in[4];
    const float* b_hh_l0f = (const float*)d_in[5];
    const float* w_ih_l0b = (const float*)d_in[6];
    const float* w_hh_l0b = (const float*)d_in[7];
    const float* b_ih_l0b = (const float*)d_in[8];
    const float* b_hh_l0b = (const float*)d_in[9];
    const float* w_ih_l1f = (const float*)d_in[10];
    const float* w_hh_l1f = (const float*)d_in[11];
    const float* b_ih_l1f = (const float*)d_in[12];
    const float* b_hh_l1f = (const float*)d_in[13];
    const float* w_ih_l1b = (const float*)d_in[14];
    const float* w_hh_l1b = (const float*)d_in[15];
    const float* b_ih_l1b = (const float*)d_in[16];
    const float* b_hh_l1b = (const float*)d_in[17];
    const float* fc1_w    = (const float*)d_in[18];
    const float* fc1_b    = (const float*)d_in[19];
    const float* fc2_w    = (const float*)d_in[20];
    const float* fc2_b    = (const float*)d_in[21];

    const size_t smem_bytes = (size_t)SMEM_FLOATS * sizeof(float);   // ~216 KB
    static bool attr_done = false;
    if (!attr_done) {
        cudaFuncSetAttribute((const void*)lstm_persistent_kernel,
                             cudaFuncAttributeMaxDynamicSharedMemorySize, (int)smem_bytes);
        attr_done = true;
    }

    transpose_x_kernel<<<(Tn * Dn * Bn + 255) / 256, 256>>>(x);

    lstm_persistent_kernel<<<NBLK, NTHR, smem_bytes>>>(
        w_ih_l0f, w_hh_l0f, b_ih_l0f, b_hh_l0f,
        w_ih_l0b, w_hh_l0b, b_ih_l0b, b_hh_l0b,
        w_ih_l1f, w_hh_l1f, b_ih_l1f, b_hh_l1f,
        w_ih_l1b, w_hh_l1b, b_ih_l1b, b_hh_l1b,
        lengths);

    head_kernel<<<Bn, 256>>>(fc1_w, fc1_b, fc2_w, fc2_b, (float*)d_out);
}